// round 15
// baseline (speedup 1.0000x reference)
#include <cuda_runtime.h>
#include <cuda_bf16.h>
#include <math.h>

#define BB   64
#define TT   512
#define DD   1024
#define HH   1024
#define N3H  3072
#define MM   (BB * TT)     // 32768
#define KP   512           // K/2 packed u32 pairs

// ---------------------------------------------------------------------------
// Scratch (device globals)
// ---------------------------------------------------------------------------
__device__ float    g_gi[(size_t)MM * N3H];
__device__ unsigned g_xhi[(size_t)MM * KP];
__device__ unsigned g_xlo[(size_t)MM * KP];
__device__ unsigned g_wihhi[(size_t)N3H * KP];
__device__ unsigned g_wihlo[(size_t)N3H * KP];
__device__ unsigned g_whhhi[(size_t)N3H * KP];
__device__ unsigned g_whhlo[(size_t)N3H * KP];
// chunked layout: idx = (kp>>4)*1024 + batch*16 + (kp&15), kp = u32 k-pair
__device__ unsigned g_hhi[2][BB * KP];
__device__ unsigned g_hlo[2][BB * KP];
__device__ unsigned g_bar;
__device__ unsigned g_work0;               // Q0 tile queue (all blocks)
__device__ unsigned g_work1;               // Q1-3 tile queue (worker blocks)
__device__ unsigned g_qcnt[4];             // per-quarter completed-tile counts

// ---------------------------------------------------------------------------
// helpers
// ---------------------------------------------------------------------------
__device__ __forceinline__ void pack2(float v0, float v1, unsigned& hi, unsigned& lo)
{
    __nv_bfloat16 h0 = __float2bfloat16(v0);
    __nv_bfloat16 h1 = __float2bfloat16(v1);
    float r0 = v0 - __bfloat162float(h0);
    float r1 = v1 - __bfloat162float(h1);
    __nv_bfloat16 l0 = __float2bfloat16(r0);
    __nv_bfloat16 l1 = __float2bfloat16(r1);
    hi = (unsigned)__bfloat16_as_ushort(h0) | ((unsigned)__bfloat16_as_ushort(h1) << 16);
    lo = (unsigned)__bfloat16_as_ushort(l0) | ((unsigned)__bfloat16_as_ushort(l1) << 16);
}

__device__ __forceinline__ void mma_bf16(float* d,
    unsigned a0, unsigned a1, unsigned a2, unsigned a3,
    unsigned b0, unsigned b1)
{
    asm volatile(
        "mma.sync.aligned.m16n8k16.row.col.f32.bf16.bf16.f32 "
        "{%0,%1,%2,%3},{%4,%5,%6,%7},{%8,%9},{%0,%1,%2,%3};\n"
        : "+f"(d[0]), "+f"(d[1]), "+f"(d[2]), "+f"(d[3])
        : "r"(a0), "r"(a1), "r"(a2), "r"(a3), "r"(b0), "r"(b1));
}

__device__ __forceinline__ void ldsm_x4(unsigned& r0, unsigned& r1, unsigned& r2, unsigned& r3,
                                        unsigned saddr)
{
    asm volatile("ldmatrix.sync.aligned.m8n8.x4.shared.b16 {%0,%1,%2,%3}, [%4];\n"
                 : "=r"(r0), "=r"(r1), "=r"(r2), "=r"(r3) : "r"(saddr));
}

__device__ __forceinline__ void ldsm_x2(unsigned& r0, unsigned& r1, unsigned saddr)
{
    asm volatile("ldmatrix.sync.aligned.m8n8.x2.shared.b16 {%0,%1}, [%2];\n"
                 : "=r"(r0), "=r"(r1) : "r"(saddr));
}

__device__ __forceinline__ void cp_async16(unsigned saddr, const void* gptr)
{
    asm volatile("cp.async.cg.shared.global [%0], [%1], 16;\n" :: "r"(saddr), "l"(gptr));
}
#define CP_COMMIT()  asm volatile("cp.async.commit_group;\n" ::: "memory")
#define CP_WAIT(N)   asm volatile("cp.async.wait_group %0;\n" :: "n"(N) : "memory")

__device__ __forceinline__ float sigf(float x) { return 1.0f / (1.0f + expf(-x)); }

__device__ __forceinline__ unsigned ld_acquire_u32(unsigned* p)
{
    unsigned v;
    asm volatile("ld.acquire.gpu.u32 %0, [%1];" : "=r"(v) : "l"(p) : "memory");
    return v;
}

__device__ __forceinline__ void red_release_add(unsigned* p, unsigned v)
{
    asm volatile("red.release.gpu.add.u32 [%0], %1;" :: "l"(p), "r"(v) : "memory");
}

// ---------------------------------------------------------------------------
// Fused prep (R9 + queue resets)
// ---------------------------------------------------------------------------
#define NB_X     65536
#define NB_W     6144
#define NB_H0    128
#define B_WIH    (NB_X)
#define B_WHH    (NB_X + NB_W)
#define B_H0     (NB_X + 2 * NB_W)
#define B_BAR    (B_H0 + NB_H0)
#define NB_PREP  (B_BAR + 1)

__global__ __launch_bounds__(256) void prep_kernel(
    const float* __restrict__ x,
    const float* __restrict__ h0,
    const int*   __restrict__ dones,
    const float* __restrict__ Wih,
    const float* __restrict__ Whh)
{
    const int blk = blockIdx.x;
    const int tid = threadIdx.x;

    if (blk < B_WIH) {
        size_t i = (size_t)blk * 256 + tid;
        float2 v = ((const float2*)x)[i];
        unsigned h, l; pack2(v.x, v.y, h, l);
        g_xhi[i] = h; g_xlo[i] = l;
    } else if (blk < B_WHH) {
        size_t i = (size_t)(blk - B_WIH) * 256 + tid;
        float2 v = ((const float2*)Wih)[i];
        unsigned h, l; pack2(v.x, v.y, h, l);
        g_wihhi[i] = h; g_wihlo[i] = l;
    } else if (blk < B_H0) {
        size_t i = (size_t)(blk - B_WHH) * 256 + tid;
        float2 v = ((const float2*)Whh)[i];
        unsigned h, l; pack2(v.x, v.y, h, l);
        g_whhhi[i] = h; g_whhlo[i] = l;
    } else if (blk < B_BAR) {
        int i = (blk - B_H0) * 256 + tid;
        int b = i >> 9, p = i & 511;
        float v0 = h0[b * HH + 2 * p];
        float v1 = h0[b * HH + 2 * p + 1];
        float m = 1.0f - (float)dones[b * TT];
        unsigned h, l; pack2(v0 * m, v1 * m, h, l);
        int idx = (p >> 4) * 1024 + b * 16 + (p & 15);
        g_hhi[0][idx] = h; g_hlo[0][idx] = l;
    } else {
        if (tid == 0) { g_bar = 0u; g_work0 = 0u; g_work1 = 1536u; }
        if (tid < 4) g_qcnt[tid] = 0u;
    }
}

// ---------------------------------------------------------------------------
// gi tile (R9 gi GEMM body as device function): M=128,N=128,K=1024, 3 passes.
// tile tl in [0,6144): q=tl/1536, r=tl%1536, b=r/24, nt=r%24
//   m0 = (b*4+q)*128 (batch b, timesteps [q*128, q*128+128)), n0 = nt*128
// ---------------------------------------------------------------------------
#define GI_ARR 5120
#define GI_AH  0
#define GI_AL  (1 * GI_ARR)
#define GI_BH  (2 * GI_ARR)
#define GI_BL  (3 * GI_ARR)
#define GI_SMEM_U32 (4 * GI_ARR)          // 20480 u32 = 81920 B

__device__ __forceinline__ void gi_issue(unsigned smem_sa, int m0, int n0,
                                         int lrow, int lq, int c, int b)
{
    size_t abase = (size_t)(m0 + lrow) * KP + c * 16 + lq;
    size_t bbase = (size_t)(n0 + lrow) * KP + c * 16 + lq;
    unsigned o = (unsigned)(b * 2560 + lrow * 20 + lq) * 4;
    cp_async16(smem_sa + GI_AH * 4 + o, &g_xhi[abase]);
    cp_async16(smem_sa + GI_AL * 4 + o, &g_xlo[abase]);
    cp_async16(smem_sa + GI_BH * 4 + o, &g_wihhi[bbase]);
    cp_async16(smem_sa + GI_BL * 4 + o, &g_wihlo[bbase]);
    CP_COMMIT();
}

__device__ void gi_tile(unsigned tl, unsigned* gsm, unsigned smem_sa,
                        const float* __restrict__ bias)
{
    const unsigned qq = tl / 1536u;
    const unsigned rr = tl - qq * 1536u;
    const unsigned bb = rr / 24u;
    const unsigned nn = rr - bb * 24u;
    const int m0 = (int)(bb * 4u + qq) * 128;
    const int n0 = (int)nn * 128;

    const int tid  = threadIdx.x;
    const int lane = tid & 31;
    const int wid  = tid >> 5;
    const int mw   = (wid & 3) * 32;
    const int nw   = (wid >> 2) * 32;
    const int g    = lane >> 2;
    const int t4   = lane & 3;

    float Da[8][4], Db[8][4];
#pragma unroll
    for (int i = 0; i < 8; ++i)
#pragma unroll
        for (int j = 0; j < 4; ++j) { Da[i][j] = 0.f; Db[i][j] = 0.f; }

    const int lrow = tid >> 2;
    const int lq   = (tid & 3) * 4;

    gi_issue(smem_sa, m0, n0, lrow, lq, 0, 0);

    for (int c = 0; c < 32; ++c) {
        if (c < 31) {
            gi_issue(smem_sa, m0, n0, lrow, lq, c + 1, (c + 1) & 1);
            CP_WAIT(1);
        } else {
            CP_WAIT(0);
        }
        __syncthreads();
        const int bo = (c & 1) * 2560;

#pragma unroll
        for (int kt = 0; kt < 2; ++kt) {
            const int o = kt * 8;
            unsigned ahi[2][4], alo[2][4], bhi[4][2];
#pragma unroll
            for (int mt = 0; mt < 2; ++mt) {
                int r = mw + mt * 16 + g;
                ahi[mt][0] = gsm[GI_AH + bo + r * 20 + o + t4];
                ahi[mt][1] = gsm[GI_AH + bo + (r + 8) * 20 + o + t4];
                ahi[mt][2] = gsm[GI_AH + bo + r * 20 + o + 4 + t4];
                ahi[mt][3] = gsm[GI_AH + bo + (r + 8) * 20 + o + 4 + t4];
                alo[mt][0] = gsm[GI_AL + bo + r * 20 + o + t4];
                alo[mt][1] = gsm[GI_AL + bo + (r + 8) * 20 + o + t4];
                alo[mt][2] = gsm[GI_AL + bo + r * 20 + o + 4 + t4];
                alo[mt][3] = gsm[GI_AL + bo + (r + 8) * 20 + o + 4 + t4];
            }
#pragma unroll
            for (int nt = 0; nt < 4; ++nt) {
                int rn = nw + nt * 8 + g;
                bhi[nt][0] = gsm[GI_BH + bo + rn * 20 + o + t4];
                bhi[nt][1] = gsm[GI_BH + bo + rn * 20 + o + 4 + t4];
            }
#pragma unroll
            for (int nt = 0; nt < 4; ++nt)
#pragma unroll
                for (int mt = 0; mt < 2; ++mt)
                    mma_bf16(Da[nt * 2 + mt], ahi[mt][0], ahi[mt][1], ahi[mt][2], ahi[mt][3],
                             bhi[nt][0], bhi[nt][1]);
#pragma unroll
            for (int nt = 0; nt < 4; ++nt)
#pragma unroll
                for (int mt = 0; mt < 2; ++mt)
                    mma_bf16(Db[nt * 2 + mt], alo[mt][0], alo[mt][1], alo[mt][2], alo[mt][3],
                             bhi[nt][0], bhi[nt][1]);
#pragma unroll
            for (int nt = 0; nt < 4; ++nt) {
                int rn = nw + nt * 8 + g;
                unsigned bl0 = gsm[GI_BL + bo + rn * 20 + o + t4];
                unsigned bl1 = gsm[GI_BL + bo + rn * 20 + o + 4 + t4];
#pragma unroll
                for (int mt = 0; mt < 2; ++mt)
                    mma_bf16(Db[nt * 2 + mt], ahi[mt][0], ahi[mt][1], ahi[mt][2], ahi[mt][3],
                             bl0, bl1);
            }
        }
        __syncthreads();
    }

#pragma unroll
    for (int nt = 0; nt < 4; ++nt) {
        int col = n0 + nw + nt * 8 + 2 * t4;
        float bs0 = bias[col], bs1 = bias[col + 1];
#pragma unroll
        for (int mt = 0; mt < 2; ++mt) {
            int idx = nt * 2 + mt;
            int row = m0 + mw + mt * 16 + g;
            g_gi[(size_t)row * N3H + col]           = Da[idx][0] + Db[idx][0] + bs0;
            g_gi[(size_t)row * N3H + col + 1]       = Da[idx][1] + Db[idx][1] + bs1;
            g_gi[(size_t)(row + 8) * N3H + col]     = Da[idx][2] + Db[idx][2] + bs0;
            g_gi[(size_t)(row + 8) * N3H + col + 1] = Da[idx][3] + Db[idx][3] + bs1;
        }
    }
}

// one queue-draining pass; all 512 threads cooperate per tile
__device__ void gi_drain(unsigned* queue, unsigned limit, unsigned* gsm,
                         unsigned smem_sa, const float* __restrict__ bias)
{
    unsigned* bc = gsm + GI_SMEM_U32;      // broadcast slot (past staging)
    while (true) {
        if (threadIdx.x == 0) bc[0] = atomicAdd(queue, 1u);
        __syncthreads();
        unsigned tl = bc[0];
        __syncthreads();
        if (tl >= limit) break;
        gi_tile(tl, gsm, smem_sa, bias);
        __syncthreads();
        if (threadIdx.x == 0) red_release_add(&g_qcnt[tl / 1536u], 1u);
    }
}

// ---------------------------------------------------------------------------
// Fused persistent kernel: 148 blocks x 512 threads.
// Blocks 0..127: Q0 gi tiles -> gate -> R9 scan (with quarter gates).
// Blocks 128..147: drain Q0 then Q1-3 gi tiles, exit.
// ---------------------------------------------------------------------------
#define SW_STRIDE 516
#define SW_U32    (2 * 24 * SW_STRIDE)
#define SA_WARP   2048
#define SCAN_SMEM_BYTES ((SW_U32 + 16 * SA_WARP) * 4)   // 230144

__global__ __launch_bounds__(512, 1) void fused_kernel(
    const float* __restrict__ h0in,
    const int*   __restrict__ dones,
    const float* __restrict__ bhh,
    const float* __restrict__ bias,
    float*       __restrict__ out)
{
    extern __shared__ unsigned smem[];
    const unsigned smem_sa = (unsigned)__cvta_generic_to_shared(smem);

    // ---- phase 1: gi work ----
    if (blockIdx.x >= 128) {
        gi_drain(&g_work0, 1536u, smem, smem_sa, bias);
        gi_drain(&g_work1, 6144u, smem, smem_sa, bias);
        return;
    }
    gi_drain(&g_work0, 1536u, smem, smem_sa, bias);

    // gate: quarter 0 complete
    if (threadIdx.x == 0) {
        while (ld_acquire_u32(&g_qcnt[0]) < 1536u) { }
    }
    __syncthreads();

    // ---- phase 2: R9 scan ----
    unsigned* sW  = smem;
    float*    red = (float*)(smem + SW_U32);
    const unsigned sW_sa = smem_sa;
    const unsigned sA_sa = smem_sa + SW_U32 * 4;

    float* hlast = out + (size_t)MM * HH;

    const int tid  = threadIdx.x;
    const int lane = tid & 31;
    const int wid  = tid >> 5;
    const int g    = lane >> 2;
    const int t4   = lane & 3;
    const int kh   = wid >> 1;
    const int mh   = wid & 1;
    const int j0   = blockIdx.x * 8;
    const unsigned warp_sa = sA_sa + wid * SA_WARP * 4;

#pragma unroll
    for (int q = 0; q < 12; ++q) {
        int id  = q * 512 + tid;
        int arr = (id >= 3072);
        int rem = id - arr * 3072;
        int rr  = rem >> 7;
        int c4  = (rem & 127) << 2;
        const unsigned* src = arr ? g_whhlo : g_whhhi;
        uint4 v = *(const uint4*)&src[(size_t)((rr >> 3) * HH + j0 + (rr & 7)) * KP + c4];
        *(uint4*)&sW[arr * (24 * SW_STRIDE) + rr * SW_STRIDE + c4] = v;
    }

    const int arow = lane & 15;
    const int qsel = lane >> 4;
    const int xr   = (arow >> 1) & 3;
    const int wrow4 = ((lane >> 4) & 1) * 8 + (lane & 7);
    const int wca4  = ((lane >> 3) & 1) * 4;
    const int wrow2 = 16 + (lane & 7);
    const int wca2  = (((lane & 15) >> 3) & 1) * 4;
    const unsigned w4h = sW_sa + (0 * (24 * SW_STRIDE) + wrow4 * SW_STRIDE + wca4) * 4;
    const unsigned w4l = sW_sa + (1 * (24 * SW_STRIDE) + wrow4 * SW_STRIDE + wca4) * 4;
    const unsigned w2h = sW_sa + (0 * (24 * SW_STRIDE) + wrow2 * SW_STRIDE + wca2) * 4;
    const unsigned w2l = sW_sa + (1 * (24 * SW_STRIDE) + wrow2 * SW_STRIDE + wca2) * 4;
    const int kbase = kh * 64;

    const int je = j0 + 2 * t4;
    const float br0 = bhh[je],          br1 = bhh[je + 1];
    const float bz0 = bhh[HH + je],     bz1 = bhh[HH + je + 1];
    const float bn0 = bhh[2 * HH + je], bn1 = bhh[2 * HH + je + 1];
    const int eb  = wid * 8 + g;
    const int emh = (eb >> 5) & 1;
    const int emt = (eb >> 4) & 1;
    const int ech = (eb >> 3) & 1;
    float hp0 = 0.f, hp1 = 0.f;
    float2 egr = make_float2(0.f, 0.f), egz = make_float2(0.f, 0.f), egn = make_float2(0.f, 0.f);
    int ed0 = 0, ed1 = 0;
    if (wid < 8) {
        float2 hv = *(const float2*)&h0in[eb * HH + je];
        hp0 = hv.x; hp1 = hv.y;
        const float* gip = g_gi + ((size_t)eb * TT + 0) * N3H;
        egr = *(const float2*)&gip[je];
        egz = *(const float2*)&gip[HH + je];
        egn = *(const float2*)&gip[2 * HH + je];
        ed0 = dones[eb * TT + 0];
        ed1 = dones[eb * TT + 1];
    }
    __syncthreads();

    for (int t = 0; t < TT; ++t) {
        const int par = t & 1;
        const unsigned* __restrict__ hh = g_hhi[par];
        const unsigned* __restrict__ hl = g_hlo[par];

        float D[2][3][4];
#pragma unroll
        for (int mt = 0; mt < 2; ++mt)
#pragma unroll
            for (int nt = 0; nt < 3; ++nt)
#pragma unroll
                for (int c = 0; c < 4; ++c) D[mt][nt][c] = 0.f;

#pragma unroll
        for (int pre = 0; pre < 2; ++pre) {
#pragma unroll
            for (int q2 = 0; q2 < 8; ++q2) {
                int i   = q2 * 32 + lane;
                int arr = i >> 7;
                int rem = i & 127;
                int row = rem >> 2;
                int cq  = rem & 3;
                const unsigned* src = (arr ? hl : hh)
                    + (size_t)(kh * 4 + pre) * 1024 + (mh * 32 + row) * 16 + cq * 4;
                unsigned dst = warp_sa
                    + (((pre * 2 + arr) * 32 + row) * 16
                       + ((cq ^ ((row >> 1) & 3)) << 2)) * 4;
                cp_async16(dst, src);
            }
            CP_COMMIT();
        }

#pragma unroll
        for (int ch = 0; ch < 4; ++ch) {
            if (ch < 3) { CP_WAIT(1); } else { CP_WAIT(0); }
            __syncwarp();
            const int buf = ch & 1;

#pragma unroll
            for (int k2 = 0; k2 < 2; ++k2) {
                const unsigned swz = (unsigned)((((k2 * 2 + qsel) ^ xr) & 3) << 2) * 4;
                unsigned AH[2][4], AL[2][4];
#pragma unroll
                for (int mt = 0; mt < 2; ++mt) {
                    unsigned abH = warp_sa + (((buf * 2 + 0) * 32 + mt * 16 + arow) * 16) * 4 + swz;
                    unsigned abL = warp_sa + (((buf * 2 + 1) * 32 + mt * 16 + arow) * 16) * 4 + swz;
                    ldsm_x4(AH[mt][0], AH[mt][1], AH[mt][2], AH[mt][3], abH);
                    ldsm_x4(AL[mt][0], AL[mt][1], AL[mt][2], AL[mt][3], abL);
                }
                const unsigned kb = (unsigned)(kbase + ch * 16 + k2 * 8) * 4;
                unsigned bh[6], bl[6];
                ldsm_x4(bh[0], bh[1], bh[2], bh[3], w4h + kb);
                ldsm_x2(bh[4], bh[5],               w2h + kb);
                ldsm_x4(bl[0], bl[1], bl[2], bl[3], w4l + kb);
                ldsm_x2(bl[4], bl[5],               w2l + kb);

#pragma unroll
                for (int nt = 0; nt < 3; ++nt)
#pragma unroll
                    for (int mt = 0; mt < 2; ++mt)
                        mma_bf16(D[mt][nt], AH[mt][0], AH[mt][1], AH[mt][2], AH[mt][3],
                                 bh[nt * 2], bh[nt * 2 + 1]);
#pragma unroll
                for (int nt = 0; nt < 3; ++nt)
#pragma unroll
                    for (int mt = 0; mt < 2; ++mt)
                        mma_bf16(D[mt][nt], AH[mt][0], AH[mt][1], AH[mt][2], AH[mt][3],
                                 bl[nt * 2], bl[nt * 2 + 1]);
#pragma unroll
                for (int nt = 0; nt < 3; ++nt)
#pragma unroll
                    for (int mt = 0; mt < 2; ++mt)
                        mma_bf16(D[mt][nt], AL[mt][0], AL[mt][1], AL[mt][2], AL[mt][3],
                                 bh[nt * 2], bh[nt * 2 + 1]);
            }
            __syncwarp();
            if (ch < 2) {
                const int nc = ch + 2;
#pragma unroll
                for (int q2 = 0; q2 < 8; ++q2) {
                    int i   = q2 * 32 + lane;
                    int arr = i >> 7;
                    int rem = i & 127;
                    int row = rem >> 2;
                    int cq  = rem & 3;
                    const unsigned* src = (arr ? hl : hh)
                        + (size_t)(kh * 4 + nc) * 1024 + (mh * 32 + row) * 16 + cq * 4;
                    unsigned dst = warp_sa
                        + ((((nc & 1) * 2 + arr) * 32 + row) * 16
                           + ((cq ^ ((row >> 1) & 3)) << 2)) * 4;
                    cp_async16(dst, src);
                }
                CP_COMMIT();
            }
        }

        __syncthreads();
#pragma unroll
        for (int mt = 0; mt < 2; ++mt)
#pragma unroll
            for (int nt = 0; nt < 3; ++nt)
#pragma unroll
                for (int c = 0; c < 4; ++c)
                    red[(wid * 24 + (mt * 3 + nt) * 4 + c) * 32 + lane] = D[mt][nt][c];
        __syncthreads();

        if (wid < 8) {
            float s[6];
#pragma unroll
            for (int gg = 0; gg < 3; ++gg)
#pragma unroll
                for (int bit = 0; bit < 2; ++bit) {
                    const int idx = (emt * 3 + gg) * 4 + ech * 2 + bit;
                    float acc = 0.f;
#pragma unroll
                    for (int k8 = 0; k8 < 8; ++k8)
                        acc += red[((k8 * 2 + emh) * 24 + idx) * 32 + lane];
                    s[gg * 2 + bit] = acc;
                }

            const float m = 1.0f - (float)ed0;
            const float h0v = hp0 * m, h1v = hp1 * m;

            float r0 = sigf(egr.x + s[0] + br0);
            float r1 = sigf(egr.y + s[1] + br1);
            float z0 = sigf(egz.x + s[2] + bz0);
            float z1 = sigf(egz.y + s[3] + bz1);
            float n0 = tanhf(egn.x + r0 * (s[4] + bn0));
            float n1 = tanhf(egn.y + r1 * (s[5] + bn1));
            float hn0 = (1.f - z0) * n0 + z0 * h0v;
            float hn1 = (1.f - z1) * n1 + z1 * h1v;

            float2 o2; o2.x = hn0; o2.y = hn1;
            *(float2*)&out[((size_t)eb * TT + t) * HH + je] = o2;
            hp0 = hn0; hp1 = hn1;

            float nm = 1.0f - (float)ed1;
            unsigned ph, pl;
            pack2(hn0 * nm, hn1 * nm, ph, pl);
            int kp  = (j0 >> 1) + t4;
            int idx = (kp >> 4) * 1024 + eb * 16 + (kp & 15);
            g_hhi[par ^ 1][idx] = ph;
            g_hlo[par ^ 1][idx] = pl;

            if (t == TT - 1)
                *(float2*)&hlast[eb * HH + je] = o2;

            // prefetch epilogue operands for t+1 (gate on gi quarter if crossing)
            if (t + 1 < TT) {
                if (((t + 1) & 127) == 0) {
                    const unsigned qq = (unsigned)((t + 1) >> 7);
                    while (ld_acquire_u32(&g_qcnt[qq]) < 1536u) { }
                }
                const float* gip = g_gi + ((size_t)eb * TT + (t + 1)) * N3H;
                egr = *(const float2*)&gip[je];
                egz = *(const float2*)&gip[HH + je];
                egn = *(const float2*)&gip[2 * HH + je];
                ed0 = dones[eb * TT + t + 1];
                ed1 = (t + 2 < TT) ? dones[eb * TT + t + 2] : 0;
            }
        }

        __syncthreads();
        if (t + 1 < TT) {
            if (tid == 0) {
                red_release_add(&g_bar, 1u);
                const unsigned target = 128u * (unsigned)(t + 1);
                while (ld_acquire_u32(&g_bar) < target) { }
            }
            __syncthreads();
        }
    }
}

// ---------------------------------------------------------------------------
// launch
// ---------------------------------------------------------------------------
extern "C" void kernel_launch(void* const* d_in, const int* in_sizes, int n_in,
                              void* d_out, int out_size)
{
    const float* x     = (const float*)d_in[0];
    const float* h0    = (const float*)d_in[1];
    const int*   dones = (const int*)  d_in[2];
    const float* Wih   = (const float*)d_in[3];
    const float* Whh   = (const float*)d_in[4];
    const float* bih   = (const float*)d_in[5];
    const float* bhh   = (const float*)d_in[6];

    float* out = (float*)d_out;

    cudaFuncSetAttribute(fused_kernel, cudaFuncAttributeMaxDynamicSharedMemorySize,
                         SCAN_SMEM_BYTES);

    prep_kernel<<<NB_PREP, 256>>>(x, h0, dones, Wih, Whh);

    fused_kernel<<<148, 512, SCAN_SMEM_BYTES>>>(h0, dones, bhh, bih, out);
}

// round 16
// speedup vs baseline: 2.5520x; 2.5520x over previous
#include <cuda_runtime.h>
#include <cuda_bf16.h>
#include <math.h>

#define BB   64
#define TT   512
#define DD   1024
#define HH   1024
#define N3H  3072
#define MM   (BB * TT)     // 32768
#define KP   512           // K/2 packed u32 pairs

// ---------------------------------------------------------------------------
// Scratch (device globals)
// ---------------------------------------------------------------------------
__device__ float    g_gi[(size_t)MM * N3H];
__device__ unsigned g_xhi[(size_t)MM * KP];
__device__ unsigned g_xlo[(size_t)MM * KP];
__device__ unsigned g_wihhi[(size_t)N3H * KP];
__device__ unsigned g_wihlo[(size_t)N3H * KP];
__device__ unsigned g_whhhi[(size_t)N3H * KP];
__device__ unsigned g_whhlo[(size_t)N3H * KP];
// chunked layout: idx = (kp>>4)*1024 + batch*16 + (kp&15), kp = u32 k-pair
__device__ unsigned g_hhi[2][BB * KP];
__device__ unsigned g_hlo[2][BB * KP];
__device__ unsigned g_bar;

// ---------------------------------------------------------------------------
// helpers
// ---------------------------------------------------------------------------
__device__ __forceinline__ void pack2(float v0, float v1, unsigned& hi, unsigned& lo)
{
    __nv_bfloat16 h0 = __float2bfloat16(v0);
    __nv_bfloat16 h1 = __float2bfloat16(v1);
    float r0 = v0 - __bfloat162float(h0);
    float r1 = v1 - __bfloat162float(h1);
    __nv_bfloat16 l0 = __float2bfloat16(r0);
    __nv_bfloat16 l1 = __float2bfloat16(r1);
    hi = (unsigned)__bfloat16_as_ushort(h0) | ((unsigned)__bfloat16_as_ushort(h1) << 16);
    lo = (unsigned)__bfloat16_as_ushort(l0) | ((unsigned)__bfloat16_as_ushort(l1) << 16);
}

__device__ __forceinline__ void mma_bf16(float* d,
    unsigned a0, unsigned a1, unsigned a2, unsigned a3,
    unsigned b0, unsigned b1)
{
    asm volatile(
        "mma.sync.aligned.m16n8k16.row.col.f32.bf16.bf16.f32 "
        "{%0,%1,%2,%3},{%4,%5,%6,%7},{%8,%9},{%0,%1,%2,%3};\n"
        : "+f"(d[0]), "+f"(d[1]), "+f"(d[2]), "+f"(d[3])
        : "r"(a0), "r"(a1), "r"(a2), "r"(a3), "r"(b0), "r"(b1));
}

__device__ __forceinline__ void ldsm_x4(unsigned& r0, unsigned& r1, unsigned& r2, unsigned& r3,
                                        unsigned saddr)
{
    asm volatile("ldmatrix.sync.aligned.m8n8.x4.shared.b16 {%0,%1,%2,%3}, [%4];\n"
                 : "=r"(r0), "=r"(r1), "=r"(r2), "=r"(r3) : "r"(saddr));
}

__device__ __forceinline__ void ldsm_x2(unsigned& r0, unsigned& r1, unsigned saddr)
{
    asm volatile("ldmatrix.sync.aligned.m8n8.x2.shared.b16 {%0,%1}, [%2];\n"
                 : "=r"(r0), "=r"(r1) : "r"(saddr));
}

__device__ __forceinline__ void cp_async16(unsigned saddr, const void* gptr)
{
    asm volatile("cp.async.cg.shared.global [%0], [%1], 16;\n" :: "r"(saddr), "l"(gptr));
}
#define CP_COMMIT()  asm volatile("cp.async.commit_group;\n" ::: "memory")
#define CP_WAIT(N)   asm volatile("cp.async.wait_group %0;\n" :: "n"(N) : "memory")

__device__ __forceinline__ float sigf(float x) { return 1.0f / (1.0f + expf(-x)); }

__device__ __forceinline__ unsigned ld_acquire_u32(unsigned* p)
{
    unsigned v;
    asm volatile("ld.acquire.gpu.u32 %0, [%1];" : "=r"(v) : "l"(p) : "memory");
    return v;
}

// ---------------------------------------------------------------------------
// Fused prep: packs x/Wih/Whh, packs h0 into g_hhi[0] (chunked), resets barrier.
// ---------------------------------------------------------------------------
#define NB_X     65536                    // MM*KP/256
#define NB_W     6144                     // N3H*KP/256
#define NB_H0    128                      // BB*KP/256
#define B_WIH    (NB_X)
#define B_WHH    (NB_X + NB_W)
#define B_H0     (NB_X + 2 * NB_W)
#define B_BAR    (B_H0 + NB_H0)
#define NB_PREP  (B_BAR + 1)

__global__ __launch_bounds__(256) void prep_kernel(
    const float* __restrict__ x,
    const float* __restrict__ h0,
    const int*   __restrict__ dones,
    const float* __restrict__ Wih,
    const float* __restrict__ Whh)
{
    const int blk = blockIdx.x;
    const int tid = threadIdx.x;

    if (blk < B_WIH) {                               // pack x
        size_t i = (size_t)blk * 256 + tid;
        float2 v = ((const float2*)x)[i];
        unsigned h, l; pack2(v.x, v.y, h, l);
        g_xhi[i] = h; g_xlo[i] = l;
    } else if (blk < B_WHH) {                        // pack W_ih
        size_t i = (size_t)(blk - B_WIH) * 256 + tid;
        float2 v = ((const float2*)Wih)[i];
        unsigned h, l; pack2(v.x, v.y, h, l);
        g_wihhi[i] = h; g_wihlo[i] = l;
    } else if (blk < B_H0) {                         // pack W_hh
        size_t i = (size_t)(blk - B_WHH) * 256 + tid;
        float2 v = ((const float2*)Whh)[i];
        unsigned h, l; pack2(v.x, v.y, h, l);
        g_whhhi[i] = h; g_whhlo[i] = l;
    } else if (blk < B_BAR) {                        // pack h0 (masked) chunked
        int i = (blk - B_H0) * 256 + tid;            // 0..BB*KP-1
        int b = i >> 9, p = i & 511;
        float v0 = h0[b * HH + 2 * p];
        float v1 = h0[b * HH + 2 * p + 1];
        float m = 1.0f - (float)dones[b * TT];
        unsigned h, l; pack2(v0 * m, v1 * m, h, l);
        int idx = (p >> 4) * 1024 + b * 16 + (p & 15);
        g_hhi[0][idx] = h; g_hlo[0][idx] = l;
    } else {
        if (tid == 0) g_bar = 0u;
    }
}

// ---------------------------------------------------------------------------
// gi GEMM (R9, proven): cp.async double-buffered, 3 bf16 hi/lo passes.
// ---------------------------------------------------------------------------
#define GI_ARR 5120
#define GI_AH  0
#define GI_AL  (1 * GI_ARR)
#define GI_BH  (2 * GI_ARR)
#define GI_BL  (3 * GI_ARR)
#define GI_SMEM_U32 (4 * GI_ARR)

__device__ __forceinline__ void gi_issue(unsigned smem_sa, int m0, int n0,
                                         int lrow, int lq, int c, int b)
{
    size_t abase = (size_t)(m0 + lrow) * KP + c * 16 + lq;
    size_t bbase = (size_t)(n0 + lrow) * KP + c * 16 + lq;
    unsigned o = (unsigned)(b * 2560 + lrow * 20 + lq) * 4;
    cp_async16(smem_sa + GI_AH * 4 + o, &g_xhi[abase]);
    cp_async16(smem_sa + GI_AL * 4 + o, &g_xlo[abase]);
    cp_async16(smem_sa + GI_BH * 4 + o, &g_wihhi[bbase]);
    cp_async16(smem_sa + GI_BL * 4 + o, &g_wihlo[bbase]);
    CP_COMMIT();
}

__global__ __launch_bounds__(512) void gi_gemm_kernel(const float* __restrict__ bias)
{
    extern __shared__ unsigned gsm[];
    const unsigned smem_sa = (unsigned)__cvta_generic_to_shared(gsm);

    const int tid  = threadIdx.x;
    const int lane = tid & 31;
    const int wid  = tid >> 5;
    const int n0   = blockIdx.x * 128;
    const int m0   = blockIdx.y * 128;
    const int mw   = (wid & 3) * 32;
    const int nw   = (wid >> 2) * 32;
    const int g    = lane >> 2;
    const int t4   = lane & 3;

    float Da[8][4], Db[8][4];
#pragma unroll
    for (int i = 0; i < 8; ++i)
#pragma unroll
        for (int j = 0; j < 4; ++j) { Da[i][j] = 0.f; Db[i][j] = 0.f; }

    const int lrow = tid >> 2;
    const int lq   = (tid & 3) * 4;

    gi_issue(smem_sa, m0, n0, lrow, lq, 0, 0);

    for (int c = 0; c < 32; ++c) {
        if (c < 31) {
            gi_issue(smem_sa, m0, n0, lrow, lq, c + 1, (c + 1) & 1);
            CP_WAIT(1);
        } else {
            CP_WAIT(0);
        }
        __syncthreads();
        const int bo = (c & 1) * 2560;

#pragma unroll
        for (int kt = 0; kt < 2; ++kt) {
            const int o = kt * 8;
            unsigned ahi[2][4], alo[2][4], bhi[4][2];
#pragma unroll
            for (int mt = 0; mt < 2; ++mt) {
                int r = mw + mt * 16 + g;
                ahi[mt][0] = gsm[GI_AH + bo + r * 20 + o + t4];
                ahi[mt][1] = gsm[GI_AH + bo + (r + 8) * 20 + o + t4];
                ahi[mt][2] = gsm[GI_AH + bo + r * 20 + o + 4 + t4];
                ahi[mt][3] = gsm[GI_AH + bo + (r + 8) * 20 + o + 4 + t4];
                alo[mt][0] = gsm[GI_AL + bo + r * 20 + o + t4];
                alo[mt][1] = gsm[GI_AL + bo + (r + 8) * 20 + o + t4];
                alo[mt][2] = gsm[GI_AL + bo + r * 20 + o + 4 + t4];
                alo[mt][3] = gsm[GI_AL + bo + (r + 8) * 20 + o + 4 + t4];
            }
#pragma unroll
            for (int nt = 0; nt < 4; ++nt) {
                int rn = nw + nt * 8 + g;
                bhi[nt][0] = gsm[GI_BH + bo + rn * 20 + o + t4];
                bhi[nt][1] = gsm[GI_BH + bo + rn * 20 + o + 4 + t4];
            }
#pragma unroll
            for (int nt = 0; nt < 4; ++nt)
#pragma unroll
                for (int mt = 0; mt < 2; ++mt)
                    mma_bf16(Da[nt * 2 + mt], ahi[mt][0], ahi[mt][1], ahi[mt][2], ahi[mt][3],
                             bhi[nt][0], bhi[nt][1]);
#pragma unroll
            for (int nt = 0; nt < 4; ++nt)
#pragma unroll
                for (int mt = 0; mt < 2; ++mt)
                    mma_bf16(Db[nt * 2 + mt], alo[mt][0], alo[mt][1], alo[mt][2], alo[mt][3],
                             bhi[nt][0], bhi[nt][1]);
#pragma unroll
            for (int nt = 0; nt < 4; ++nt) {
                int rn = nw + nt * 8 + g;
                unsigned bl0 = gsm[GI_BL + bo + rn * 20 + o + t4];
                unsigned bl1 = gsm[GI_BL + bo + rn * 20 + o + 4 + t4];
#pragma unroll
                for (int mt = 0; mt < 2; ++mt)
                    mma_bf16(Db[nt * 2 + mt], ahi[mt][0], ahi[mt][1], ahi[mt][2], ahi[mt][3],
                             bl0, bl1);
            }
        }
        __syncthreads();
    }

#pragma unroll
    for (int nt = 0; nt < 4; ++nt) {
        int col = n0 + nw + nt * 8 + 2 * t4;
        float bs0 = bias[col], bs1 = bias[col + 1];
#pragma unroll
        for (int mt = 0; mt < 2; ++mt) {
            int idx = nt * 2 + mt;
            int row = m0 + mw + mt * 16 + g;
            g_gi[(size_t)row * N3H + col]           = Da[idx][0] + Db[idx][0] + bs0;
            g_gi[(size_t)row * N3H + col + 1]       = Da[idx][1] + Db[idx][1] + bs1;
            g_gi[(size_t)(row + 8) * N3H + col]     = Da[idx][2] + Db[idx][2] + bs0;
            g_gi[(size_t)(row + 8) * N3H + col + 1] = Da[idx][3] + Db[idx][3] + bs1;
        }
    }
}

// ---------------------------------------------------------------------------
// Persistent GRU scan (R9 champion, verbatim): 128 blocks x 512 threads.
// warp = (kh 0..7, mh 0..1); per-warp cp.async staging; ldmatrix fragments;
// h in epilogue registers; gi/dones prefetched for t+1 before the barrier.
// SMEM: sW 2*24*516 u32 (99072B) + sA 16*2048 u32 (131072B) = 230144 B.
// ---------------------------------------------------------------------------
#define SW_STRIDE 516
#define SW_U32    (2 * 24 * SW_STRIDE)
#define SA_WARP   2048

__global__ __launch_bounds__(512, 1) void gru_scan_kernel(
    const float* __restrict__ h0in,
    const int*   __restrict__ dones,
    const float* __restrict__ bhh,
    float*       __restrict__ out)
{
    extern __shared__ unsigned smem[];
    unsigned* sW  = smem;
    float*    red = (float*)(smem + SW_U32);       // aliases A staging

    const unsigned smem_sa = (unsigned)__cvta_generic_to_shared(smem);
    const unsigned sW_sa   = smem_sa;
    const unsigned sA_sa   = smem_sa + SW_U32 * 4;

    float* hlast = out + (size_t)MM * HH;

    const int tid  = threadIdx.x;
    const int lane = tid & 31;
    const int wid  = tid >> 5;
    const int g    = lane >> 2;
    const int t4   = lane & 3;
    const int kh   = wid >> 1;
    const int mh   = wid & 1;
    const int j0   = blockIdx.x * 8;
    const unsigned warp_sa = sA_sa + wid * SA_WARP * 4;

    // ---- load W_hh slice into SMEM (once) ----
#pragma unroll
    for (int q = 0; q < 12; ++q) {
        int id  = q * 512 + tid;                   // 0..6143 uint4
        int arr = (id >= 3072);
        int rem = id - arr * 3072;
        int rr  = rem >> 7;                        // 0..23
        int c4  = (rem & 127) << 2;
        const unsigned* src = arr ? g_whhlo : g_whhhi;
        uint4 v = *(const uint4*)&src[(size_t)((rr >> 3) * HH + j0 + (rr & 7)) * KP + c4];
        *(uint4*)&sW[arr * (24 * SW_STRIDE) + rr * SW_STRIDE + c4] = v;
    }

    // ---- ldmatrix address precomputes ----
    const int arow = lane & 15;
    const int qsel = lane >> 4;
    const int xr   = (arow >> 1) & 3;
    const int wrow4 = ((lane >> 4) & 1) * 8 + (lane & 7);
    const int wca4  = ((lane >> 3) & 1) * 4;
    const int wrow2 = 16 + (lane & 7);
    const int wca2  = (((lane & 15) >> 3) & 1) * 4;
    const unsigned w4h = sW_sa + (0 * (24 * SW_STRIDE) + wrow4 * SW_STRIDE + wca4) * 4;
    const unsigned w4l = sW_sa + (1 * (24 * SW_STRIDE) + wrow4 * SW_STRIDE + wca4) * 4;
    const unsigned w2h = sW_sa + (0 * (24 * SW_STRIDE) + wrow2 * SW_STRIDE + wca2) * 4;
    const unsigned w2l = sW_sa + (1 * (24 * SW_STRIDE) + wrow2 * SW_STRIDE + wca2) * 4;
    const int kbase = kh * 64;

    // ---- epilogue constants + register h (first 8 warps) ----
    const int je = j0 + 2 * t4;
    const float br0 = bhh[je],          br1 = bhh[je + 1];
    const float bz0 = bhh[HH + je],     bz1 = bhh[HH + je + 1];
    const float bn0 = bhh[2 * HH + je], bn1 = bhh[2 * HH + je + 1];
    const int eb  = wid * 8 + g;                   // wid<8 only
    const int emh = (eb >> 5) & 1;
    const int emt = (eb >> 4) & 1;
    const int ech = (eb >> 3) & 1;
    float hp0 = 0.f, hp1 = 0.f;
    float2 egr = make_float2(0.f, 0.f), egz = make_float2(0.f, 0.f), egn = make_float2(0.f, 0.f);
    int ed0 = 0, ed1 = 0;
    if (wid < 8) {
        float2 hv = *(const float2*)&h0in[eb * HH + je];
        hp0 = hv.x; hp1 = hv.y;
        const float* gip = g_gi + ((size_t)eb * TT + 0) * N3H;
        egr = *(const float2*)&gip[je];
        egz = *(const float2*)&gip[HH + je];
        egn = *(const float2*)&gip[2 * HH + je];
        ed0 = dones[eb * TT + 0];
        ed1 = dones[eb * TT + 1];
    }
    __syncthreads();

    for (int t = 0; t < TT; ++t) {
        const int par = t & 1;
        const unsigned* __restrict__ hh = g_hhi[par];
        const unsigned* __restrict__ hl = g_hlo[par];

        float D[2][3][4];
#pragma unroll
        for (int mt = 0; mt < 2; ++mt)
#pragma unroll
            for (int nt = 0; nt < 3; ++nt)
#pragma unroll
                for (int c = 0; c < 4; ++c) D[mt][nt][c] = 0.f;

        // issue chunks 0 and 1
#pragma unroll
        for (int pre = 0; pre < 2; ++pre) {
#pragma unroll
            for (int q2 = 0; q2 < 8; ++q2) {
                int i   = q2 * 32 + lane;
                int arr = i >> 7;
                int rem = i & 127;
                int row = rem >> 2;
                int cq  = rem & 3;
                const unsigned* src = (arr ? hl : hh)
                    + (size_t)(kh * 4 + pre) * 1024 + (mh * 32 + row) * 16 + cq * 4;
                unsigned dst = warp_sa
                    + (((pre * 2 + arr) * 32 + row) * 16
                       + ((cq ^ ((row >> 1) & 3)) << 2)) * 4;
                cp_async16(dst, src);
            }
            CP_COMMIT();
        }

#pragma unroll
        for (int ch = 0; ch < 4; ++ch) {
            if (ch < 3) { CP_WAIT(1); } else { CP_WAIT(0); }
            __syncwarp();
            const int buf = ch & 1;

#pragma unroll
            for (int k2 = 0; k2 < 2; ++k2) {
                const unsigned swz = (unsigned)((((k2 * 2 + qsel) ^ xr) & 3) << 2) * 4;
                unsigned AH[2][4], AL[2][4];
#pragma unroll
                for (int mt = 0; mt < 2; ++mt) {
                    unsigned abH = warp_sa + (((buf * 2 + 0) * 32 + mt * 16 + arow) * 16) * 4 + swz;
                    unsigned abL = warp_sa + (((buf * 2 + 1) * 32 + mt * 16 + arow) * 16) * 4 + swz;
                    ldsm_x4(AH[mt][0], AH[mt][1], AH[mt][2], AH[mt][3], abH);
                    ldsm_x4(AL[mt][0], AL[mt][1], AL[mt][2], AL[mt][3], abL);
                }
                const unsigned kb = (unsigned)(kbase + ch * 16 + k2 * 8) * 4;
                unsigned bh[6], bl[6];
                ldsm_x4(bh[0], bh[1], bh[2], bh[3], w4h + kb);
                ldsm_x2(bh[4], bh[5],               w2h + kb);
                ldsm_x4(bl[0], bl[1], bl[2], bl[3], w4l + kb);
                ldsm_x2(bl[4], bl[5],               w2l + kb);

#pragma unroll
                for (int nt = 0; nt < 3; ++nt)
#pragma unroll
                    for (int mt = 0; mt < 2; ++mt)
                        mma_bf16(D[mt][nt], AH[mt][0], AH[mt][1], AH[mt][2], AH[mt][3],
                                 bh[nt * 2], bh[nt * 2 + 1]);
#pragma unroll
                for (int nt = 0; nt < 3; ++nt)
#pragma unroll
                    for (int mt = 0; mt < 2; ++mt)
                        mma_bf16(D[mt][nt], AH[mt][0], AH[mt][1], AH[mt][2], AH[mt][3],
                                 bl[nt * 2], bl[nt * 2 + 1]);
#pragma unroll
                for (int nt = 0; nt < 3; ++nt)
#pragma unroll
                    for (int mt = 0; mt < 2; ++mt)
                        mma_bf16(D[mt][nt], AL[mt][0], AL[mt][1], AL[mt][2], AL[mt][3],
                                 bh[nt * 2], bh[nt * 2 + 1]);
            }
            __syncwarp();
            if (ch < 2) {
                const int nc = ch + 2;
#pragma unroll
                for (int q2 = 0; q2 < 8; ++q2) {
                    int i   = q2 * 32 + lane;
                    int arr = i >> 7;
                    int rem = i & 127;
                    int row = rem >> 2;
                    int cq  = rem & 3;
                    const unsigned* src = (arr ? hl : hh)
                        + (size_t)(kh * 4 + nc) * 1024 + (mh * 32 + row) * 16 + cq * 4;
                    unsigned dst = warp_sa
                        + ((((nc & 1) * 2 + arr) * 32 + row) * 16
                           + ((cq ^ ((row >> 1) & 3)) << 2)) * 4;
                    cp_async16(dst, src);
                }
                CP_COMMIT();
            }
        }

        // ---- K reduction across 8 kh slices (red aliases A staging) ----
        __syncthreads();
#pragma unroll
        for (int mt = 0; mt < 2; ++mt)
#pragma unroll
            for (int nt = 0; nt < 3; ++nt)
#pragma unroll
                for (int c = 0; c < 4; ++c)
                    red[(wid * 24 + (mt * 3 + nt) * 4 + c) * 32 + lane] = D[mt][nt][c];
        __syncthreads();

        // ---- epilogue on first 8 warps ----
        if (wid < 8) {
            float s[6];
#pragma unroll
            for (int gg = 0; gg < 3; ++gg)
#pragma unroll
                for (int bit = 0; bit < 2; ++bit) {
                    const int idx = (emt * 3 + gg) * 4 + ech * 2 + bit;
                    float acc = 0.f;
#pragma unroll
                    for (int k8 = 0; k8 < 8; ++k8)
                        acc += red[((k8 * 2 + emh) * 24 + idx) * 32 + lane];
                    s[gg * 2 + bit] = acc;
                }

            const float m = 1.0f - (float)ed0;
            const float h0v = hp0 * m, h1v = hp1 * m;

            float r0 = sigf(egr.x + s[0] + br0);
            float r1 = sigf(egr.y + s[1] + br1);
            float z0 = sigf(egz.x + s[2] + bz0);
            float z1 = sigf(egz.y + s[3] + bz1);
            float n0 = tanhf(egn.x + r0 * (s[4] + bn0));
            float n1 = tanhf(egn.y + r1 * (s[5] + bn1));
            float hn0 = (1.f - z0) * n0 + z0 * h0v;
            float hn1 = (1.f - z1) * n1 + z1 * h1v;

            float2 o2; o2.x = hn0; o2.y = hn1;
            *(float2*)&out[((size_t)eb * TT + t) * HH + je] = o2;
            hp0 = hn0; hp1 = hn1;

            float nm = 1.0f - (float)ed1;
            unsigned ph, pl;
            pack2(hn0 * nm, hn1 * nm, ph, pl);
            int kp  = (j0 >> 1) + t4;
            int idx = (kp >> 4) * 1024 + eb * 16 + (kp & 15);
            g_hhi[par ^ 1][idx] = ph;
            g_hlo[par ^ 1][idx] = pl;

            if (t == TT - 1)
                *(float2*)&hlast[eb * HH + je] = o2;

            // ---- prefetch epilogue operands for t+1 (overlaps barrier wait) ----
            if (t + 1 < TT) {
                const float* gip = g_gi + ((size_t)eb * TT + (t + 1)) * N3H;
                egr = *(const float2*)&gip[je];
                egz = *(const float2*)&gip[HH + je];
                egn = *(const float2*)&gip[2 * HH + je];
                ed0 = dones[eb * TT + t + 1];
                ed1 = (t + 2 < TT) ? dones[eb * TT + t + 2] : 0;
            }
        }

        // ---- grid barrier ----
        __syncthreads();
        if (t + 1 < TT) {
            if (tid == 0) {
                asm volatile("red.release.gpu.add.u32 [%0], %1;"
                             :: "l"(&g_bar), "r"(1u) : "memory");
                const unsigned target = 128u * (unsigned)(t + 1);
                while (ld_acquire_u32(&g_bar) < target) { }
            }
            __syncthreads();
        }
    }
}

// ---------------------------------------------------------------------------
// launch
// ---------------------------------------------------------------------------
extern "C" void kernel_launch(void* const* d_in, const int* in_sizes, int n_in,
                              void* d_out, int out_size)
{
    const float* x     = (const float*)d_in[0];
    const float* h0    = (const float*)d_in[1];
    const int*   dones = (const int*)  d_in[2];
    const float* Wih   = (const float*)d_in[3];
    const float* Whh   = (const float*)d_in[4];
    const float* bih   = (const float*)d_in[5];
    const float* bhh   = (const float*)d_in[6];

    float* out = (float*)d_out;

    const int GI_SMEM   = GI_SMEM_U32 * 4;               // 81920 B
    const int SCAN_SMEM = (SW_U32 + 16 * SA_WARP) * 4;   // 230144 B
    cudaFuncSetAttribute(gi_gemm_kernel,  cudaFuncAttributeMaxDynamicSharedMemorySize, GI_SMEM);
    cudaFuncSetAttribute(gru_scan_kernel, cudaFuncAttributeMaxDynamicSharedMemorySize, SCAN_SMEM);

    prep_kernel<<<NB_PREP, 256>>>(x, h0, dones, Wih, Whh);

    {
        dim3 grid(N3H / 128, MM / 128);
        gi_gemm_kernel<<<grid, 512, GI_SMEM>>>(bih);
    }

    gru_scan_kernel<<<128, 512, SCAN_SMEM>>>(h0, dones, bhh, out);
}

// round 17
// speedup vs baseline: 2.6206x; 1.0269x over previous
#include <cuda_runtime.h>
#include <cuda_bf16.h>
#include <math.h>

#define BB   64
#define TT   512
#define DD   1024
#define HH   1024
#define N3H  3072
#define MM   (BB * TT)     // 32768
#define KP   512           // K/2 packed u32 pairs

// ---------------------------------------------------------------------------
// Scratch (device globals)
// ---------------------------------------------------------------------------
__device__ float    g_gi[(size_t)MM * N3H];
__device__ unsigned g_xhi[(size_t)MM * KP];
__device__ unsigned g_xlo[(size_t)MM * KP];
__device__ unsigned g_wihhi[(size_t)N3H * KP];
__device__ unsigned g_wihlo[(size_t)N3H * KP];
__device__ unsigned g_whhhi[(size_t)N3H * KP];
__device__ unsigned g_whhlo[(size_t)N3H * KP];
// chunked layout: idx = (kp>>4)*1024 + batch*16 + (kp&15), kp = u32 k-pair
__device__ unsigned g_hhi[2][BB * KP];
__device__ unsigned g_hlo[2][BB * KP];
__device__ unsigned g_bar;

// ---------------------------------------------------------------------------
// helpers
// ---------------------------------------------------------------------------
__device__ __forceinline__ void pack2(float v0, float v1, unsigned& hi, unsigned& lo)
{
    __nv_bfloat16 h0 = __float2bfloat16(v0);
    __nv_bfloat16 h1 = __float2bfloat16(v1);
    float r0 = v0 - __bfloat162float(h0);
    float r1 = v1 - __bfloat162float(h1);
    __nv_bfloat16 l0 = __float2bfloat16(r0);
    __nv_bfloat16 l1 = __float2bfloat16(r1);
    hi = (unsigned)__bfloat16_as_ushort(h0) | ((unsigned)__bfloat16_as_ushort(h1) << 16);
    lo = (unsigned)__bfloat16_as_ushort(l0) | ((unsigned)__bfloat16_as_ushort(l1) << 16);
}

__device__ __forceinline__ void mma_bf16(float* d,
    unsigned a0, unsigned a1, unsigned a2, unsigned a3,
    unsigned b0, unsigned b1)
{
    asm volatile(
        "mma.sync.aligned.m16n8k16.row.col.f32.bf16.bf16.f32 "
        "{%0,%1,%2,%3},{%4,%5,%6,%7},{%8,%9},{%0,%1,%2,%3};\n"
        : "+f"(d[0]), "+f"(d[1]), "+f"(d[2]), "+f"(d[3])
        : "r"(a0), "r"(a1), "r"(a2), "r"(a3), "r"(b0), "r"(b1));
}

__device__ __forceinline__ void ldsm_x4(unsigned& r0, unsigned& r1, unsigned& r2, unsigned& r3,
                                        unsigned saddr)
{
    asm volatile("ldmatrix.sync.aligned.m8n8.x4.shared.b16 {%0,%1,%2,%3}, [%4];\n"
                 : "=r"(r0), "=r"(r1), "=r"(r2), "=r"(r3) : "r"(saddr));
}

__device__ __forceinline__ void ldsm_x2(unsigned& r0, unsigned& r1, unsigned saddr)
{
    asm volatile("ldmatrix.sync.aligned.m8n8.x2.shared.b16 {%0,%1}, [%2];\n"
                 : "=r"(r0), "=r"(r1) : "r"(saddr));
}

__device__ __forceinline__ void cp_async16(unsigned saddr, const void* gptr)
{
    asm volatile("cp.async.cg.shared.global [%0], [%1], 16;\n" :: "r"(saddr), "l"(gptr));
}
#define CP_COMMIT()  asm volatile("cp.async.commit_group;\n" ::: "memory")
#define CP_WAIT(N)   asm volatile("cp.async.wait_group %0;\n" :: "n"(N) : "memory")

__device__ __forceinline__ float sigf(float x) { return 1.0f / (1.0f + expf(-x)); }

__device__ __forceinline__ unsigned ld_acquire_u32(unsigned* p)
{
    unsigned v;
    asm volatile("ld.acquire.gpu.u32 %0, [%1];" : "=r"(v) : "l"(p) : "memory");
    return v;
}

// ---------------------------------------------------------------------------
// Fused prep: packs x/Wih/Whh, packs h0 into g_hhi[0] (chunked), resets barrier.
// ---------------------------------------------------------------------------
#define NB_X     65536                    // MM*KP/256
#define NB_W     6144                     // N3H*KP/256
#define NB_H0    128                      // BB*KP/256
#define B_WIH    (NB_X)
#define B_WHH    (NB_X + NB_W)
#define B_H0     (NB_X + 2 * NB_W)
#define B_BAR    (B_H0 + NB_H0)
#define NB_PREP  (B_BAR + 1)

__global__ __launch_bounds__(256) void prep_kernel(
    const float* __restrict__ x,
    const float* __restrict__ h0,
    const int*   __restrict__ dones,
    const float* __restrict__ Wih,
    const float* __restrict__ Whh)
{
    const int blk = blockIdx.x;
    const int tid = threadIdx.x;

    if (blk < B_WIH) {                               // pack x
        size_t i = (size_t)blk * 256 + tid;
        float2 v = ((const float2*)x)[i];
        unsigned h, l; pack2(v.x, v.y, h, l);
        g_xhi[i] = h; g_xlo[i] = l;
    } else if (blk < B_WHH) {                        // pack W_ih
        size_t i = (size_t)(blk - B_WIH) * 256 + tid;
        float2 v = ((const float2*)Wih)[i];
        unsigned h, l; pack2(v.x, v.y, h, l);
        g_wihhi[i] = h; g_wihlo[i] = l;
    } else if (blk < B_H0) {                         // pack W_hh
        size_t i = (size_t)(blk - B_WHH) * 256 + tid;
        float2 v = ((const float2*)Whh)[i];
        unsigned h, l; pack2(v.x, v.y, h, l);
        g_whhhi[i] = h; g_whhlo[i] = l;
    } else if (blk < B_BAR) {                        // pack h0 (masked) chunked
        int i = (blk - B_H0) * 256 + tid;            // 0..BB*KP-1
        int b = i >> 9, p = i & 511;
        float v0 = h0[b * HH + 2 * p];
        float v1 = h0[b * HH + 2 * p + 1];
        float m = 1.0f - (float)dones[b * TT];
        unsigned h, l; pack2(v0 * m, v1 * m, h, l);
        int idx = (p >> 4) * 1024 + b * 16 + (p & 15);
        g_hhi[0][idx] = h; g_hlo[0][idx] = l;
    } else {
        if (tid == 0) g_bar = 0u;
    }
}

// ---------------------------------------------------------------------------
// gi GEMM v5: R9 structure + ldmatrix fragment loads (scan-proven mapping,
// row stride 20 u32 -> conflict-free: (5*row + col/4) mod 8 all-distinct).
// ---------------------------------------------------------------------------
#define GI_ARR 5120
#define GI_AH  0
#define GI_AL  (1 * GI_ARR)
#define GI_BH  (2 * GI_ARR)
#define GI_BL  (3 * GI_ARR)
#define GI_SMEM_U32 (4 * GI_ARR)

__device__ __forceinline__ void gi_issue(unsigned smem_sa, int m0, int n0,
                                         int lrow, int lq, int c, int b)
{
    size_t abase = (size_t)(m0 + lrow) * KP + c * 16 + lq;
    size_t bbase = (size_t)(n0 + lrow) * KP + c * 16 + lq;
    unsigned o = (unsigned)(b * 2560 + lrow * 20 + lq) * 4;
    cp_async16(smem_sa + GI_AH * 4 + o, &g_xhi[abase]);
    cp_async16(smem_sa + GI_AL * 4 + o, &g_xlo[abase]);
    cp_async16(smem_sa + GI_BH * 4 + o, &g_wihhi[bbase]);
    cp_async16(smem_sa + GI_BL * 4 + o, &g_wihlo[bbase]);
    CP_COMMIT();
}

__global__ __launch_bounds__(512) void gi_gemm_kernel(const float* __restrict__ bias)
{
    extern __shared__ unsigned gsm[];
    const unsigned smem_sa = (unsigned)__cvta_generic_to_shared(gsm);

    const int tid  = threadIdx.x;
    const int lane = tid & 31;
    const int wid  = tid >> 5;
    const int n0   = blockIdx.x * 128;
    const int m0   = blockIdx.y * 128;
    const int mw   = (wid & 3) * 32;
    const int nw   = (wid >> 2) * 32;
    const int g    = lane >> 2;
    const int t4   = lane & 3;

    float Da[8][4], Db[8][4];
#pragma unroll
    for (int i = 0; i < 8; ++i)
#pragma unroll
        for (int j = 0; j < 4; ++j) { Da[i][j] = 0.f; Db[i][j] = 0.f; }

    const int lrow = tid >> 2;
    const int lq   = (tid & 3) * 4;

    // ldmatrix per-lane base offsets (u32), within one buffer
    const unsigned a_off = (unsigned)((mw + (lane & 15)) * 20 + (lane >> 4) * 4);
    const unsigned b_off = (unsigned)((nw + ((lane >> 4) & 1) * 8 + (lane & 7)) * 20
                                      + ((lane >> 3) & 1) * 4);
    const unsigned aH_base = smem_sa + (GI_AH + a_off) * 4;
    const unsigned aL_base = smem_sa + (GI_AL + a_off) * 4;
    const unsigned bH_base = smem_sa + (GI_BH + b_off) * 4;
    const unsigned bL_base = smem_sa + (GI_BL + b_off) * 4;

    gi_issue(smem_sa, m0, n0, lrow, lq, 0, 0);

    for (int c = 0; c < 32; ++c) {
        if (c < 31) {
            gi_issue(smem_sa, m0, n0, lrow, lq, c + 1, (c + 1) & 1);
            CP_WAIT(1);
        } else {
            CP_WAIT(0);
        }
        __syncthreads();
        const unsigned bo4 = (unsigned)((c & 1) * 2560) * 4;

#pragma unroll
        for (int kt = 0; kt < 2; ++kt) {
            const unsigned o4 = (unsigned)(kt * 8) * 4;
            unsigned ahi[2][4], alo[2][4], bhi[2][4], blo[2][4];
#pragma unroll
            for (int mt = 0; mt < 2; ++mt) {
                const unsigned moff = bo4 + (unsigned)(mt * 16 * 20) * 4 + o4;
                ldsm_x4(ahi[mt][0], ahi[mt][1], ahi[mt][2], ahi[mt][3], aH_base + moff);
                ldsm_x4(alo[mt][0], alo[mt][1], alo[mt][2], alo[mt][3], aL_base + moff);
            }
#pragma unroll
            for (int p = 0; p < 2; ++p) {
                const unsigned poff = bo4 + (unsigned)(p * 16 * 20) * 4 + o4;
                ldsm_x4(bhi[p][0], bhi[p][1], bhi[p][2], bhi[p][3], bH_base + poff);
                ldsm_x4(blo[p][0], blo[p][1], blo[p][2], blo[p][3], bL_base + poff);
            }

#pragma unroll
            for (int nt = 0; nt < 4; ++nt) {
                const int p = nt >> 1, q = (nt & 1) * 2;
#pragma unroll
                for (int mt = 0; mt < 2; ++mt)
                    mma_bf16(Da[nt * 2 + mt], ahi[mt][0], ahi[mt][1], ahi[mt][2], ahi[mt][3],
                             bhi[p][q], bhi[p][q + 1]);
            }
#pragma unroll
            for (int nt = 0; nt < 4; ++nt) {
                const int p = nt >> 1, q = (nt & 1) * 2;
#pragma unroll
                for (int mt = 0; mt < 2; ++mt)
                    mma_bf16(Db[nt * 2 + mt], alo[mt][0], alo[mt][1], alo[mt][2], alo[mt][3],
                             bhi[p][q], bhi[p][q + 1]);
            }
#pragma unroll
            for (int nt = 0; nt < 4; ++nt) {
                const int p = nt >> 1, q = (nt & 1) * 2;
#pragma unroll
                for (int mt = 0; mt < 2; ++mt)
                    mma_bf16(Db[nt * 2 + mt], ahi[mt][0], ahi[mt][1], ahi[mt][2], ahi[mt][3],
                             blo[p][q], blo[p][q + 1]);
            }
        }
        __syncthreads();
    }

#pragma unroll
    for (int nt = 0; nt < 4; ++nt) {
        int col = n0 + nw + nt * 8 + 2 * t4;
        float bs0 = bias[col], bs1 = bias[col + 1];
#pragma unroll
        for (int mt = 0; mt < 2; ++mt) {
            int idx = nt * 2 + mt;
            int row = m0 + mw + mt * 16 + g;
            g_gi[(size_t)row * N3H + col]           = Da[idx][0] + Db[idx][0] + bs0;
            g_gi[(size_t)row * N3H + col + 1]       = Da[idx][1] + Db[idx][1] + bs1;
            g_gi[(size_t)(row + 8) * N3H + col]     = Da[idx][2] + Db[idx][2] + bs0;
            g_gi[(size_t)(row + 8) * N3H + col + 1] = Da[idx][3] + Db[idx][3] + bs1;
        }
    }
}

// ---------------------------------------------------------------------------
// Persistent GRU scan (R9 champion, verbatim): 128 blocks x 512 threads.
// ---------------------------------------------------------------------------
#define SW_STRIDE 516
#define SW_U32    (2 * 24 * SW_STRIDE)
#define SA_WARP   2048

__global__ __launch_bounds__(512, 1) void gru_scan_kernel(
    const float* __restrict__ h0in,
    const int*   __restrict__ dones,
    const float* __restrict__ bhh,
    float*       __restrict__ out)
{
    extern __shared__ unsigned smem[];
    unsigned* sW  = smem;
    float*    red = (float*)(smem + SW_U32);       // aliases A staging

    const unsigned smem_sa = (unsigned)__cvta_generic_to_shared(smem);
    const unsigned sW_sa   = smem_sa;
    const unsigned sA_sa   = smem_sa + SW_U32 * 4;

    float* hlast = out + (size_t)MM * HH;

    const int tid  = threadIdx.x;
    const int lane = tid & 31;
    const int wid  = tid >> 5;
    const int g    = lane >> 2;
    const int t4   = lane & 3;
    const int kh   = wid >> 1;
    const int mh   = wid & 1;
    const int j0   = blockIdx.x * 8;
    const unsigned warp_sa = sA_sa + wid * SA_WARP * 4;

    // ---- load W_hh slice into SMEM (once) ----
#pragma unroll
    for (int q = 0; q < 12; ++q) {
        int id  = q * 512 + tid;                   // 0..6143 uint4
        int arr = (id >= 3072);
        int rem = id - arr * 3072;
        int rr  = rem >> 7;                        // 0..23
        int c4  = (rem & 127) << 2;
        const unsigned* src = arr ? g_whhlo : g_whhhi;
        uint4 v = *(const uint4*)&src[(size_t)((rr >> 3) * HH + j0 + (rr & 7)) * KP + c4];
        *(uint4*)&sW[arr * (24 * SW_STRIDE) + rr * SW_STRIDE + c4] = v;
    }

    // ---- ldmatrix address precomputes ----
    const int arow = lane & 15;
    const int qsel = lane >> 4;
    const int xr   = (arow >> 1) & 3;
    const int wrow4 = ((lane >> 4) & 1) * 8 + (lane & 7);
    const int wca4  = ((lane >> 3) & 1) * 4;
    const int wrow2 = 16 + (lane & 7);
    const int wca2  = (((lane & 15) >> 3) & 1) * 4;
    const unsigned w4h = sW_sa + (0 * (24 * SW_STRIDE) + wrow4 * SW_STRIDE + wca4) * 4;
    const unsigned w4l = sW_sa + (1 * (24 * SW_STRIDE) + wrow4 * SW_STRIDE + wca4) * 4;
    const unsigned w2h = sW_sa + (0 * (24 * SW_STRIDE) + wrow2 * SW_STRIDE + wca2) * 4;
    const unsigned w2l = sW_sa + (1 * (24 * SW_STRIDE) + wrow2 * SW_STRIDE + wca2) * 4;
    const int kbase = kh * 64;

    // ---- epilogue constants + register h (first 8 warps) ----
    const int je = j0 + 2 * t4;
    const float br0 = bhh[je],          br1 = bhh[je + 1];
    const float bz0 = bhh[HH + je],     bz1 = bhh[HH + je + 1];
    const float bn0 = bhh[2 * HH + je], bn1 = bhh[2 * HH + je + 1];
    const int eb  = wid * 8 + g;                   // wid<8 only
    const int emh = (eb >> 5) & 1;
    const int emt = (eb >> 4) & 1;
    const int ech = (eb >> 3) & 1;
    float hp0 = 0.f, hp1 = 0.f;
    float2 egr = make_float2(0.f, 0.f), egz = make_float2(0.f, 0.f), egn = make_float2(0.f, 0.f);
    int ed0 = 0, ed1 = 0;
    if (wid < 8) {
        float2 hv = *(const float2*)&h0in[eb * HH + je];
        hp0 = hv.x; hp1 = hv.y;
        const float* gip = g_gi + ((size_t)eb * TT + 0) * N3H;
        egr = *(const float2*)&gip[je];
        egz = *(const float2*)&gip[HH + je];
        egn = *(const float2*)&gip[2 * HH + je];
        ed0 = dones[eb * TT + 0];
        ed1 = dones[eb * TT + 1];
    }
    __syncthreads();

    for (int t = 0; t < TT; ++t) {
        const int par = t & 1;
        const unsigned* __restrict__ hh = g_hhi[par];
        const unsigned* __restrict__ hl = g_hlo[par];

        float D[2][3][4];
#pragma unroll
        for (int mt = 0; mt < 2; ++mt)
#pragma unroll
            for (int nt = 0; nt < 3; ++nt)
#pragma unroll
                for (int c = 0; c < 4; ++c) D[mt][nt][c] = 0.f;

        // issue chunks 0 and 1
#pragma unroll
        for (int pre = 0; pre < 2; ++pre) {
#pragma unroll
            for (int q2 = 0; q2 < 8; ++q2) {
                int i   = q2 * 32 + lane;
                int arr = i >> 7;
                int rem = i & 127;
                int row = rem >> 2;
                int cq  = rem & 3;
                const unsigned* src = (arr ? hl : hh)
                    + (size_t)(kh * 4 + pre) * 1024 + (mh * 32 + row) * 16 + cq * 4;
                unsigned dst = warp_sa
                    + (((pre * 2 + arr) * 32 + row) * 16
                       + ((cq ^ ((row >> 1) & 3)) << 2)) * 4;
                cp_async16(dst, src);
            }
            CP_COMMIT();
        }

#pragma unroll
        for (int ch = 0; ch < 4; ++ch) {
            if (ch < 3) { CP_WAIT(1); } else { CP_WAIT(0); }
            __syncwarp();
            const int buf = ch & 1;

#pragma unroll
            for (int k2 = 0; k2 < 2; ++k2) {
                const unsigned swz = (unsigned)((((k2 * 2 + qsel) ^ xr) & 3) << 2) * 4;
                unsigned AH[2][4], AL[2][4];
#pragma unroll
                for (int mt = 0; mt < 2; ++mt) {
                    unsigned abH = warp_sa + (((buf * 2 + 0) * 32 + mt * 16 + arow) * 16) * 4 + swz;
                    unsigned abL = warp_sa + (((buf * 2 + 1) * 32 + mt * 16 + arow) * 16) * 4 + swz;
                    ldsm_x4(AH[mt][0], AH[mt][1], AH[mt][2], AH[mt][3], abH);
                    ldsm_x4(AL[mt][0], AL[mt][1], AL[mt][2], AL[mt][3], abL);
                }
                const unsigned kb = (unsigned)(kbase + ch * 16 + k2 * 8) * 4;
                unsigned bh[6], bl[6];
                ldsm_x4(bh[0], bh[1], bh[2], bh[3], w4h + kb);
                ldsm_x2(bh[4], bh[5],               w2h + kb);
                ldsm_x4(bl[0], bl[1], bl[2], bl[3], w4l + kb);
                ldsm_x2(bl[4], bl[5],               w2l + kb);

#pragma unroll
                for (int nt = 0; nt < 3; ++nt)
#pragma unroll
                    for (int mt = 0; mt < 2; ++mt)
                        mma_bf16(D[mt][nt], AH[mt][0], AH[mt][1], AH[mt][2], AH[mt][3],
                                 bh[nt * 2], bh[nt * 2 + 1]);
#pragma unroll
                for (int nt = 0; nt < 3; ++nt)
#pragma unroll
                    for (int mt = 0; mt < 2; ++mt)
                        mma_bf16(D[mt][nt], AH[mt][0], AH[mt][1], AH[mt][2], AH[mt][3],
                                 bl[nt * 2], bl[nt * 2 + 1]);
#pragma unroll
                for (int nt = 0; nt < 3; ++nt)
#pragma unroll
                    for (int mt = 0; mt < 2; ++mt)
                        mma_bf16(D[mt][nt], AL[mt][0], AL[mt][1], AL[mt][2], AL[mt][3],
                                 bh[nt * 2], bh[nt * 2 + 1]);
            }
            __syncwarp();
            if (ch < 2) {
                const int nc = ch + 2;
#pragma unroll
                for (int q2 = 0; q2 < 8; ++q2) {
                    int i   = q2 * 32 + lane;
                    int arr = i >> 7;
                    int rem = i & 127;
                    int row = rem >> 2;
                    int cq  = rem & 3;
                    const unsigned* src = (arr ? hl : hh)
                        + (size_t)(kh * 4 + nc) * 1024 + (mh * 32 + row) * 16 + cq * 4;
                    unsigned dst = warp_sa
                        + ((((nc & 1) * 2 + arr) * 32 + row) * 16
                           + ((cq ^ ((row >> 1) & 3)) << 2)) * 4;
                    cp_async16(dst, src);
                }
                CP_COMMIT();
            }
        }

        // ---- K reduction across 8 kh slices (red aliases A staging) ----
        __syncthreads();
#pragma unroll
        for (int mt = 0; mt < 2; ++mt)
#pragma unroll
            for (int nt = 0; nt < 3; ++nt)
#pragma unroll
                for (int c = 0; c < 4; ++c)
                    red[(wid * 24 + (mt * 3 + nt) * 4 + c) * 32 + lane] = D[mt][nt][c];
        __syncthreads();

        // ---- epilogue on first 8 warps ----
        if (wid < 8) {
            float s[6];
#pragma unroll
            for (int gg = 0; gg < 3; ++gg)
#pragma unroll
                for (int bit = 0; bit < 2; ++bit) {
                    const int idx = (emt * 3 + gg) * 4 + ech * 2 + bit;
                    float acc = 0.f;
#pragma unroll
                    for (int k8 = 0; k8 < 8; ++k8)
                        acc += red[((k8 * 2 + emh) * 24 + idx) * 32 + lane];
                    s[gg * 2 + bit] = acc;
                }

            const float m = 1.0f - (float)ed0;
            const float h0v = hp0 * m, h1v = hp1 * m;

            float r0 = sigf(egr.x + s[0] + br0);
            float r1 = sigf(egr.y + s[1] + br1);
            float z0 = sigf(egz.x + s[2] + bz0);
            float z1 = sigf(egz.y + s[3] + bz1);
            float n0 = tanhf(egn.x + r0 * (s[4] + bn0));
            float n1 = tanhf(egn.y + r1 * (s[5] + bn1));
            float hn0 = (1.f - z0) * n0 + z0 * h0v;
            float hn1 = (1.f - z1) * n1 + z1 * h1v;

            float2 o2; o2.x = hn0; o2.y = hn1;
            *(float2*)&out[((size_t)eb * TT + t) * HH + je] = o2;
            hp0 = hn0; hp1 = hn1;

            float nm = 1.0f - (float)ed1;
            unsigned ph, pl;
            pack2(hn0 * nm, hn1 * nm, ph, pl);
            int kp  = (j0 >> 1) + t4;
            int idx = (kp >> 4) * 1024 + eb * 16 + (kp & 15);
            g_hhi[par ^ 1][idx] = ph;
            g_hlo[par ^ 1][idx] = pl;

            if (t == TT - 1)
                *(float2*)&hlast[eb * HH + je] = o2;

            // ---- prefetch epilogue operands for t+1 (overlaps barrier wait) ----
            if (t + 1 < TT) {
                const float* gip = g_gi + ((size_t)eb * TT + (t + 1)) * N3H;
                egr = *(const float2*)&gip[je];
                egz = *(const float2*)&gip[HH + je];
                egn = *(const float2*)&gip[2 * HH + je];
                ed0 = dones[eb * TT + t + 1];
                ed1 = (t + 2 < TT) ? dones[eb * TT + t + 2] : 0;
            }
        }

        // ---- grid barrier ----
        __syncthreads();
        if (t + 1 < TT) {
            if (tid == 0) {
                asm volatile("red.release.gpu.add.u32 [%0], %1;"
                             :: "l"(&g_bar), "r"(1u) : "memory");
                const unsigned target = 128u * (unsigned)(t + 1);
                while (ld_acquire_u32(&g_bar) < target) { }
            }
            __syncthreads();
        }
    }
}

// ---------------------------------------------------------------------------
// launch
// ---------------------------------------------------------------------------
extern "C" void kernel_launch(void* const* d_in, const int* in_sizes, int n_in,
                              void* d_out, int out_size)
{
    const float* x     = (const float*)d_in[0];
    const float* h0    = (const float*)d_in[1];
    const int*   dones = (const int*)  d_in[2];
    const float* Wih   = (const float*)d_in[3];
    const float* Whh   = (const float*)d_in[4];
    const float* bih   = (const float*)d_in[5];
    const float* bhh   = (const float*)d_in[6];

    float* out = (float*)d_out;

    const int GI_SMEM   = GI_SMEM_U32 * 4;               // 81920 B
    const int SCAN_SMEM = (SW_U32 + 16 * SA_WARP) * 4;   // 230144 B
    cudaFuncSetAttribute(gi_gemm_kernel,  cudaFuncAttributeMaxDynamicSharedMemorySize, GI_SMEM);
    cudaFuncSetAttribute(gru_scan_kernel, cudaFuncAttributeMaxDynamicSharedMemorySize, SCAN_SMEM);

    prep_kernel<<<NB_PREP, 256>>>(x, h0, dones, Wih, Whh);

    {
        dim3 grid(N3H / 128, MM / 128);
        gi_gemm_kernel<<<grid, 512, GI_SMEM>>>(bih);
    }

    gru_scan_kernel<<<128, 512, SCAN_SMEM>>>(h0, dones, bhh, out);
}